// round 4
// baseline (speedup 1.0000x reference)
#include <cuda_runtime.h>

// LineSpectralPairsStabilityCheck: (256, 4096, 33) fp32.
// Per row of 33: keep [0]; run 4 passes of {31-step neighbor-separation scan,
// clip to [min_d, pi - min_d]} on channels [1..32]. Rows independent.
// 1 thread per row; block tile staged through shared memory so all global
// traffic is coalesced float4 with streaming (.cs) cache hints.

#define W 33
#define ROWS_PER_BLOCK 128
#define TILE_ELEMS (ROWS_PER_BLOCK * W)   // 4224 floats = 16896 B (16B-divisible)

__global__ void __launch_bounds__(ROWS_PER_BLOCK)
lsp_stability_kernel(const float* __restrict__ in, float* __restrict__ out)
{
    __shared__ float sm[TILE_ELEMS];

    const int t = threadIdx.x;
    const long long base = (long long)blockIdx.x * TILE_ELEMS;

    // ---- coalesced vectorized streaming load of the block tile ----
    const float4* __restrict__ in4 = (const float4*)(in + base);
    float4* sm4 = (float4*)sm;
    #pragma unroll
    for (int i = t; i < TILE_ELEMS / 4; i += ROWS_PER_BLOCK)
        sm4[i] = __ldcs(&in4[i]);
    __syncthreads();

    // ---- each thread owns one row (stride-33 smem: 33 % 32 == 1 -> conflict-free) ----
    float v[W];
    #pragma unroll
    for (int i = 0; i < W; i++)
        v[i] = sm[t * W + i];

    const float pi_f  = 3.14159265358979323846f;
    const float min_d = 0.01f * pi_f / 33.0f;   // RATE * pi / (LSP_ORDER + 1)
    const float hi    = pi_f - min_d;

    #pragma unroll
    for (int it = 0; it < 4; it++) {
        // scan over v[1..32]:
        //   c = v[1]
        //   for j in 2..32: s = 0.5*max(min_d - (v[j] - c), 0)
        //                   v[j-1] = c - s; c = v[j] + s
        //   v[32] = c
        float c = v[1];
        #pragma unroll
        for (int i = 2; i <= 32; i++) {
            float nxt = v[i];
            float s = 0.5f * fmaxf(min_d - (nxt - c), 0.0f);
            v[i - 1] = c - s;
            c = nxt + s;
        }
        v[32] = c;
        // clip
        #pragma unroll
        for (int i = 1; i <= 32; i++)
            v[i] = fminf(fmaxf(v[i], min_d), hi);
    }

    // ---- write row back to private smem region ----
    #pragma unroll
    for (int i = 0; i < W; i++)
        sm[t * W + i] = v[i];
    __syncthreads();

    // ---- coalesced vectorized streaming store ----
    float4* __restrict__ out4 = (float4*)(out + base);
    #pragma unroll
    for (int i = t; i < TILE_ELEMS / 4; i += ROWS_PER_BLOCK)
        __stcs(&out4[i], sm4[i]);
}

extern "C" void kernel_launch(void* const* d_in, const int* in_sizes, int n_in,
                              void* d_out, int out_size)
{
    const float* in = (const float*)d_in[0];
    float* out = (float*)d_out;

    const int total = in_sizes[0];            // 256*4096*33 = 34,603,008
    const int rows = total / W;               // 1,048,576
    const int blocks = rows / ROWS_PER_BLOCK; // 8192 (exact)

    lsp_stability_kernel<<<blocks, ROWS_PER_BLOCK>>>(in, out);
}